// round 15
// baseline (speedup 1.0000x reference)
#include <cuda_runtime.h>

#define Bn 256
#define Nn 2048
#define An 256
#define Hn 8
#define VDn 32
#define On 256

// ---- scratch (__device__ globals; no allocations allowed) ----
__device__ float g_qavg[Bn * An];          // [B][A]
__device__ float g_qk[Bn * Hn * An];       // [B][H][A]
__device__ float g_wa[Bn * Hn * VDn];      // [B][H*VD]

__device__ __forceinline__ float tf32r(float x) {
    unsigned u;
    asm("cvt.rna.tf32.f32 %0, %1;" : "=r"(u) : "f"(x));
    return __uint_as_float(u);
}

// =====================  K1: masked mean over N  =====================
__global__ void k_qavg(const float* __restrict__ qd, const float* __restrict__ qm) {
    int b = blockIdx.y, a0 = blockIdx.x * 64, t = threadIdx.x;
    __shared__ float red[256];
    const float* mb = qm + (size_t)b * Nn;
    float ms = 0.f;
    for (int n = t; n < Nn; n += 256) ms += mb[n];
    red[t] = ms; __syncthreads();
    for (int s = 128; s; s >>= 1) { if (t < s) red[t] += red[t + s]; __syncthreads(); }
    float denom = red[0] + 1e-10f;
    __syncthreads();
    int a = a0 + (t & 63), r0 = t >> 6;
    const float* qb = qd + (size_t)b * Nn * An + a;
    float acc = 0.f;
    for (int n = r0; n < Nn; n += 4) acc += mb[n] * qb[(size_t)n * An];
    red[t] = acc; __syncthreads();
    if (t < 64)
        g_qavg[b * An + a0 + t] =
            (red[t] + red[t + 64] + red[t + 128] + red[t + 192]) / denom;
}

// =====================  K2: q projection then qk = q @ key_w^T  =====================
__global__ void k_qk(const float* __restrict__ qw, const float* __restrict__ kw) {
    int b = blockIdx.x, t = threadIdx.x;
    __shared__ float qa[256], qs[256];
    qa[t] = g_qavg[b * 256 + t];
    __syncthreads();
    float acc = 0.f;
    #pragma unroll 8
    for (int a = 0; a < 256; a++) acc += qa[a] * qw[a * 256 + t]; // t = h*32+c
    qs[t] = acc * 0.17677669529663687f; // 32^-0.5
    __syncthreads();
    // t = a
    float kr[32];
    #pragma unroll
    for (int c = 0; c < 32; c += 4) {
        float4 v = *(const float4*)(kw + t * 32 + c);
        kr[c] = v.x; kr[c + 1] = v.y; kr[c + 2] = v.z; kr[c + 3] = v.w;
    }
    #pragma unroll
    for (int h = 0; h < 8; h++) {
        float s = 0.f;
        #pragma unroll
        for (int c = 0; c < 32; c++) s += qs[h * 32 + c] * kr[c];
        g_qk[(b * 8 + h) * 256 + t] = s;
    }
}

// =====================  K3: attention per batch  =====================
extern __shared__ float smem4[];
__global__ void k_attn(const float* __restrict__ md, const float* __restrict__ qm,
                       const float* __restrict__ vw) {
    float* qk_s = smem4;          // 2048 (later reused as wm[8][256])
    float* wgt = qk_s + 2048;     // 8*2048
    float* mask_s = wgt + 16384;  // 2048
    int b = blockIdx.x, t = threadIdx.x;
    int w = t >> 5, lane = t & 31;

    for (int i = t; i < 2048; i += 512) {
        qk_s[i] = g_qk[b * 2048 + i];
        mask_s[i] = qm[(size_t)b * Nn + i];
    }
    __syncthreads();
    const float* mb = md + (size_t)b * Nn * An;

    // ---- phase 1: logits[h][n] ----
    for (int n = w; n < Nn; n += 16) {
        const float* mr = mb + (size_t)n * An;
        float p[8];
        #pragma unroll
        for (int h = 0; h < 8; h++) p[h] = 0.f;
        #pragma unroll
        for (int e = 0; e < 8; e++) {
            float mv = mr[lane + 32 * e];
            #pragma unroll
            for (int h = 0; h < 8; h++) p[h] += qk_s[h * 256 + lane + 32 * e] * mv;
        }
        #pragma unroll
        for (int h = 0; h < 8; h++) {
            p[h] += __shfl_xor_sync(0xffffffffu, p[h], 1);
            p[h] += __shfl_xor_sync(0xffffffffu, p[h], 2);
        }
        int q = lane & 3;
        float v0 = p[2 * q], v1 = p[2 * q + 1];
        #pragma unroll
        for (int d = 4; d <= 16; d <<= 1) {
            v0 += __shfl_xor_sync(0xffffffffu, v0, d);
            v1 += __shfl_xor_sync(0xffffffffu, v1, d);
        }
        if (lane < 4) {
            float mbias = 1e9f * (mask_s[n] - 1.f);
            wgt[(2 * lane) * 2048 + n] = v0 + mbias;
            wgt[(2 * lane + 1) * 2048 + n] = v1 + mbias;
        }
    }
    __syncthreads();

    // ---- softmax: warp h handles row h ----
    if (w < 8) {
        float* row = wgt + w * 2048;
        float mx = -1e30f;
        for (int n = lane; n < 2048; n += 32) mx = fmaxf(mx, row[n]);
        #pragma unroll
        for (int d = 16; d; d >>= 1) mx = fmaxf(mx, __shfl_xor_sync(0xffffffffu, mx, d));
        float sm = 0.f;
        for (int n = lane; n < 2048; n += 32) {
            float e = __expf(row[n] - mx);
            row[n] = e; sm += e;
        }
        #pragma unroll
        for (int d = 16; d; d >>= 1) sm += __shfl_xor_sync(0xffffffffu, sm, d);
        float inv = 1.f / sm;
        for (int n = lane; n < 2048; n += 32) row[n] *= inv;
    }
    __syncthreads();

    // ---- phase 2: wm[h][a] = sum_n w[h][n]*m[n][a] ----
    int a = t & 255, hb = (t >> 8) * 4;
    float acc[4] = {0.f, 0.f, 0.f, 0.f};
    #pragma unroll 4
    for (int n = 0; n < 2048; n++) {
        float mv = mb[(size_t)n * An + a];
        #pragma unroll
        for (int j = 0; j < 4; j++) acc[j] += wgt[(hb + j) * 2048 + n] * mv;
    }
    float* wm = qk_s;
    #pragma unroll
    for (int j = 0; j < 4; j++) wm[(hb + j) * 256 + a] = acc[j];
    __syncthreads();

    // ---- phase 3: wa[h][c] = wm @ value_w ----
    if (t < 256) {
        int h = t >> 5, c = t & 31;
        float s = 0.f;
        #pragma unroll 8
        for (int aa = 0; aa < 256; aa++) s += wm[h * 256 + aa] * vw[aa * 32 + c];
        g_wa[b * 256 + t] = s;
    }
}

// =====================  K4: fused gate-GEMM + sigmoid*wa + out-GEMM (tf32 mma)  ==========
// CTA tile 128x256, 8 warps in a 2x4 grid, warp tile 64x64 (4x8 m16n8k8 mmas).
// Xs: [128][264] fp32 (stride 264 -> A-frag LDS.32 conflict-free).
// W double buffer: transposed [col][8 k] stride 8, k pairs (k,k+4) adjacent,
// pair index XOR-swizzled by (col>>2)&3 -> B-frag is one conflict-free LDS.64,
// chunk stores are conflict-free STS.64.
#define TM 128
#define XS2 264
#define WBUF 2048   // 256 cols * 8
#define SMEM5_FLOATS (TM * XS2 + 2 * WBUF + 3 * 256)
#define SMEM5_BYTES (SMEM5_FLOATS * 4)

__device__ __forceinline__ void gemm_tile(const float* __restrict__ Wg,
                                          const float* Xs, float* Wsm,
                                          float acc[4][8][4],
                                          int row0, int col0, int g, int tg, int t) {
    #pragma unroll
    for (int i = 0; i < 4; i++)
        #pragma unroll
        for (int jj = 0; jj < 8; jj++)
            #pragma unroll
            for (int r = 0; r < 4; r++) acc[i][jj][r] = 0.f;

    int sw = (t >> 2) & 3;
    float w0[8];
    // preload chunk 0: thread t owns column t, all 8 k-rows
    #pragma unroll
    for (int j = 0; j < 8; j++) w0[j] = Wg[j * 256 + t];
    {
        float* d = Wsm + t * 8;
        #pragma unroll
        for (int p = 0; p < 4; p++)
            *(float2*)(d + 2 * (p ^ sw)) = make_float2(tf32r(w0[p]), tf32r(w0[p + 4]));
    }
    __syncthreads();

    for (int kc = 0; kc < 32; kc++) {
        int cur = kc & 1;
        if (kc < 31) {
            const float* src = Wg + (size_t)(kc + 1) * 8 * 256 + t;
            #pragma unroll
            for (int j = 0; j < 8; j++) w0[j] = src[j * 256];
        }
        int kb = kc * 8;
        unsigned af[4][4];
        #pragma unroll
        for (int i = 0; i < 4; i++) {
            int r0 = row0 + i * 16 + g;
            af[i][0] = __float_as_uint(Xs[r0 * XS2 + kb + tg]);
            af[i][1] = __float_as_uint(Xs[(r0 + 8) * XS2 + kb + tg]);
            af[i][2] = __float_as_uint(Xs[r0 * XS2 + kb + tg + 4]);
            af[i][3] = __float_as_uint(Xs[(r0 + 8) * XS2 + kb + tg + 4]);
        }
        const float* Wb = Wsm + cur * WBUF;
        #pragma unroll
        for (int jj = 0; jj < 8; jj++) {
            int col = col0 + jj * 8 + g;
            int swc = (col >> 2) & 3;
            float2 bv = *(const float2*)(Wb + col * 8 + 2 * (tg ^ swc));
            unsigned b0 = __float_as_uint(bv.x);
            unsigned b1 = __float_as_uint(bv.y);
            #pragma unroll
            for (int i = 0; i < 4; i++) {
                asm volatile(
                    "mma.sync.aligned.m16n8k8.row.col.f32.tf32.tf32.f32 "
                    "{%0,%1,%2,%3},{%4,%5,%6,%7},{%8,%9},{%0,%1,%2,%3};"
                    : "+f"(acc[i][jj][0]), "+f"(acc[i][jj][1]),
                      "+f"(acc[i][jj][2]), "+f"(acc[i][jj][3])
                    : "r"(af[i][0]), "r"(af[i][1]), "r"(af[i][2]), "r"(af[i][3]),
                      "r"(b0), "r"(b1));
            }
        }
        if (kc < 31) {
            float* d = Wsm + (cur ^ 1) * WBUF + t * 8;
            #pragma unroll
            for (int p = 0; p < 4; p++)
                *(float2*)(d + 2 * (p ^ sw)) = make_float2(tf32r(w0[p]), tf32r(w0[p + 4]));
        }
        __syncthreads();
    }
}

extern __shared__ float sm5[];
__global__ void __launch_bounds__(256)
k_fused(const float* __restrict__ qd, const float* __restrict__ gw,
        const float* __restrict__ gb, const float* __restrict__ ow,
        const float* __restrict__ ob, float* __restrict__ out) {
    float* Xs = sm5;                 // TM*XS2
    float* Wsm = Xs + TM * XS2;      // 2*WBUF
    float* wa_s = Wsm + 2 * WBUF;    // 256
    float* gb_s = wa_s + 256;        // 256
    float* ob_s = gb_s + 256;        // 256
    int t = threadIdx.x;
    int tile = blockIdx.x;
    int b = tile >> 4;               // 16 tiles of 128 tokens per batch
    int n0 = (tile & 15) * TM;

    wa_s[t] = g_wa[b * 256 + t];
    gb_s[t] = gb[t];
    ob_s[t] = ob[t];

    // load X tile (128x256), tf32-rounded, float4 in/out
    {
        const float* xg = qd + ((size_t)b * Nn + n0) * An;
        int cb = (t & 63) * 4;
        int rr = t >> 6;
        #pragma unroll
        for (int i = 0; i < 32; i++) {
            int r = rr + 4 * i;
            float4 v = *(const float4*)(xg + (size_t)r * An + cb);
            float4 u = make_float4(tf32r(v.x), tf32r(v.y), tf32r(v.z), tf32r(v.w));
            *(float4*)(Xs + r * XS2 + cb) = u;
        }
    }

    int w = t >> 5, lane = t & 31;
    int row0 = (w & 1) * 64, col0 = (w >> 1) * 64;
    int g = lane >> 2, tg = lane & 3;

    float acc[4][8][4];

    // ---- GEMM1: X @ Wg ----
    __syncthreads();
    gemm_tile(gw, Xs, Wsm, acc, row0, col0, g, tg, t);

    // epilogue1: gate = sigmoid(acc + gb) * wa, write over Xs
    #pragma unroll
    for (int i = 0; i < 4; i++) {
        int r = row0 + i * 16 + g;
        #pragma unroll
        for (int jj = 0; jj < 8; jj++) {
            int c = col0 + jj * 8 + tg * 2;
            float w0 = wa_s[c], w1 = wa_s[c + 1];
            float b0 = gb_s[c], b1 = gb_s[c + 1];
            float v0 = w0 / (1.f + __expf(-(acc[i][jj][0] + b0)));
            float v1 = w1 / (1.f + __expf(-(acc[i][jj][1] + b1)));
            float v2 = w0 / (1.f + __expf(-(acc[i][jj][2] + b0)));
            float v3 = w1 / (1.f + __expf(-(acc[i][jj][3] + b1)));
            *(float2*)(Xs + r * XS2 + c) = make_float2(tf32r(v0), tf32r(v1));
            *(float2*)(Xs + (r + 8) * XS2 + c) = make_float2(tf32r(v2), tf32r(v3));
        }
    }
    __syncthreads();

    // ---- GEMM2: G @ Wo ----
    gemm_tile(ow, Xs, Wsm, acc, row0, col0, g, tg, t);

    // epilogue2: + output_b, store
    float* og = out + ((size_t)b * Nn + n0) * On;
    #pragma unroll
    for (int i = 0; i < 4; i++) {
        int r = row0 + i * 16 + g;
        #pragma unroll
        for (int jj = 0; jj < 8; jj++) {
            int c = col0 + jj * 8 + tg * 2;
            float2 u0 = make_float2(acc[i][jj][0] + ob_s[c], acc[i][jj][1] + ob_s[c + 1]);
            float2 u1 = make_float2(acc[i][jj][2] + ob_s[c], acc[i][jj][3] + ob_s[c + 1]);
            *(float2*)(og + (size_t)r * On + c) = u0;
            *(float2*)(og + (size_t)(r + 8) * On + c) = u1;
        }
    }
}

// =====================  launch  =====================
extern "C" void kernel_launch(void* const* d_in, const int* in_sizes, int n_in,
                              void* d_out, int out_size) {
    (void)in_sizes; (void)n_in; (void)out_size;
    const float* qd = (const float*)d_in[0];   // q_data [B,N,A]
    const float* md = (const float*)d_in[1];   // m_data [B,N,M]
    const float* qm = (const float*)d_in[2];   // q_mask [B,N,1]
    const float* qw = (const float*)d_in[4];   // query_w [A,H,KD]
    const float* kw = (const float*)d_in[5];   // key_w [M,KD]
    const float* vw = (const float*)d_in[6];   // value_w [M,VD]
    const float* gw = (const float*)d_in[7];   // gating_w [A,H,VD]
    const float* gb = (const float*)d_in[8];   // gating_b [H,VD]
    const float* ow = (const float*)d_in[9];   // output_w [H,VD,O]
    const float* ob = (const float*)d_in[10];  // output_b [O]
    float* out = (float*)d_out;

    cudaFuncSetAttribute(k_attn, cudaFuncAttributeMaxDynamicSharedMemorySize, 81920);
    cudaFuncSetAttribute(k_fused, cudaFuncAttributeMaxDynamicSharedMemorySize, SMEM5_BYTES);

    k_qavg<<<dim3(4, 256), 256>>>(qd, qm);
    k_qk<<<256, 256>>>(qw, kw);
    k_attn<<<256, 512, 81920>>>(md, qm, vw);
    k_fused<<<4096, 256, SMEM5_BYTES>>>(qd, gw, gb, ow, ob, out);
}

// round 17
// speedup vs baseline: 1.1023x; 1.1023x over previous
#include <cuda_runtime.h>
#include <cstdint>

#define Bn 256
#define Nn 2048
#define An 256

// ---- scratch (__device__ globals; no allocations allowed) ----
__device__ float g_qavg[Bn * An];          // [B][A]
__device__ float g_qk[Bn * 8 * An];        // [B][H][A]
__device__ float g_wa[Bn * 256];           // [B][H*VD]
__device__ float g_gwt[65536];             // tf32-rounded gating_w
__device__ float g_owt[65536];             // tf32-rounded output_w

__device__ __forceinline__ float tf32r(float x) {
    unsigned u;
    asm("cvt.rna.tf32.f32 %0, %1;" : "=r"(u) : "f"(x));
    return __uint_as_float(u);
}
__device__ __forceinline__ uint32_t s2u(const void* p) {
    uint32_t a;
    asm("{ .reg .u64 t; cvta.to.shared.u64 t, %1; cvt.u32.u64 %0, t; }"
        : "=r"(a) : "l"(p));
    return a;
}
__device__ __forceinline__ void cpa16(uint32_t d, const float* s) {
    asm volatile("cp.async.ca.shared.global [%0], [%1], 16;" :: "r"(d), "l"(s) : "memory");
}

// =====================  K0: pre-round weights to tf32  =====================
__global__ void k_prep(const float* __restrict__ gw, const float* __restrict__ ow) {
    int i = blockIdx.x * 256 + threadIdx.x;   // 256 blocks -> 65536
    g_gwt[i] = tf32r(gw[i]);
    g_owt[i] = tf32r(ow[i]);
}

// =====================  K1: masked mean over N  =====================
__global__ void k_qavg(const float* __restrict__ qd, const float* __restrict__ qm) {
    int b = blockIdx.y, a0 = blockIdx.x * 64, t = threadIdx.x;
    __shared__ float red[256];
    const float* mb = qm + (size_t)b * Nn;
    float ms = 0.f;
    for (int n = t; n < Nn; n += 256) ms += mb[n];
    red[t] = ms; __syncthreads();
    for (int s = 128; s; s >>= 1) { if (t < s) red[t] += red[t + s]; __syncthreads(); }
    float denom = red[0] + 1e-10f;
    __syncthreads();
    int a = a0 + (t & 63), r0 = t >> 6;
    const float* qb = qd + (size_t)b * Nn * An + a;
    float acc = 0.f;
    for (int n = r0; n < Nn; n += 4) acc += mb[n] * qb[(size_t)n * An];
    red[t] = acc; __syncthreads();
    if (t < 64)
        g_qavg[b * An + a0 + t] =
            (red[t] + red[t + 64] + red[t + 128] + red[t + 192]) / denom;
}

// =====================  K2: q projection then qk = q @ key_w^T  =====================
__global__ void k_qk(const float* __restrict__ qw, const float* __restrict__ kw) {
    int b = blockIdx.x, t = threadIdx.x;
    __shared__ float qa[256], qs[256];
    qa[t] = g_qavg[b * 256 + t];
    __syncthreads();
    float acc = 0.f;
    #pragma unroll 8
    for (int a = 0; a < 256; a++) acc += qa[a] * qw[a * 256 + t];
    qs[t] = acc * 0.17677669529663687f;
    __syncthreads();
    float kr[32];
    #pragma unroll
    for (int c = 0; c < 32; c += 4) {
        float4 v = *(const float4*)(kw + t * 32 + c);
        kr[c] = v.x; kr[c + 1] = v.y; kr[c + 2] = v.z; kr[c + 3] = v.w;
    }
    #pragma unroll
    for (int h = 0; h < 8; h++) {
        float s = 0.f;
        #pragma unroll
        for (int c = 0; c < 32; c++) s += qs[h * 32 + c] * kr[c];
        g_qk[(b * 8 + h) * 256 + t] = s;
    }
}

// =====================  K3: attention per batch  =====================
extern __shared__ float smem4[];
__global__ void k_attn(const float* __restrict__ md, const float* __restrict__ qm,
                       const float* __restrict__ vw) {
    float* qk_s = smem4;
    float* wgt = qk_s + 2048;
    float* mask_s = wgt + 16384;
    int b = blockIdx.x, t = threadIdx.x;
    int w = t >> 5, lane = t & 31;

    for (int i = t; i < 2048; i += 512) {
        qk_s[i] = g_qk[b * 2048 + i];
        mask_s[i] = qm[(size_t)b * Nn + i];
    }
    __syncthreads();
    const float* mb = md + (size_t)b * Nn * An;

    for (int n = w; n < Nn; n += 16) {
        const float* mr = mb + (size_t)n * An;
        float p[8];
        #pragma unroll
        for (int h = 0; h < 8; h++) p[h] = 0.f;
        #pragma unroll
        for (int e = 0; e < 8; e++) {
            float mv = mr[lane + 32 * e];
            #pragma unroll
            for (int h = 0; h < 8; h++) p[h] += qk_s[h * 256 + lane + 32 * e] * mv;
        }
        #pragma unroll
        for (int h = 0; h < 8; h++) {
            p[h] += __shfl_xor_sync(0xffffffffu, p[h], 1);
            p[h] += __shfl_xor_sync(0xffffffffu, p[h], 2);
        }
        int q = lane & 3;
        float v0 = p[2 * q], v1 = p[2 * q + 1];
        #pragma unroll
        for (int d = 4; d <= 16; d <<= 1) {
            v0 += __shfl_xor_sync(0xffffffffu, v0, d);
            v1 += __shfl_xor_sync(0xffffffffu, v1, d);
        }
        if (lane < 4) {
            float mbias = 1e9f * (mask_s[n] - 1.f);
            wgt[(2 * lane) * 2048 + n] = v0 + mbias;
            wgt[(2 * lane + 1) * 2048 + n] = v1 + mbias;
        }
    }
    __syncthreads();

    if (w < 8) {
        float* row = wgt + w * 2048;
        float mx = -1e30f;
        for (int n = lane; n < 2048; n += 32) mx = fmaxf(mx, row[n]);
        #pragma unroll
        for (int d = 16; d; d >>= 1) mx = fmaxf(mx, __shfl_xor_sync(0xffffffffu, mx, d));
        float sm = 0.f;
        for (int n = lane; n < 2048; n += 32) {
            float e = __expf(row[n] - mx);
            row[n] = e; sm += e;
        }
        #pragma unroll
        for (int d = 16; d; d >>= 1) sm += __shfl_xor_sync(0xffffffffu, sm, d);
        float inv = 1.f / sm;
        for (int n = lane; n < 2048; n += 32) row[n] *= inv;
    }
    __syncthreads();

    int a = t & 255, hb = (t >> 8) * 4;
    float acc[4] = {0.f, 0.f, 0.f, 0.f};
    #pragma unroll 4
    for (int n = 0; n < 2048; n++) {
        float mv = mb[(size_t)n * An + a];
        #pragma unroll
        for (int j = 0; j < 4; j++) acc[j] += wgt[(hb + j) * 2048 + n] * mv;
    }
    float* wm = qk_s;
    #pragma unroll
    for (int j = 0; j < 4; j++) wm[(hb + j) * 256 + a] = acc[j];
    __syncthreads();

    if (t < 256) {
        int h = t >> 5, c = t & 31;
        float s = 0.f;
        #pragma unroll 8
        for (int aa = 0; aa < 256; aa++) s += wm[h * 256 + aa] * vw[aa * 32 + c];
        g_wa[b * 256 + t] = s;
    }
}

// =====================  K4: fused gate+out GEMMs, tf32 mma.sync + cp.async pipeline  =====
// CTA 128x256, 8 warps, warp tile 64x64 (4x8 m16n8k8 mmas).
// Xs stride 260 (A-frag bank = 4g+tg -> conflict-free).
// W ring: 4 stages x 8 k-rows x stride 264 (B-frag bank = 8tg+g -> conflict-free).
// Unified 64-chunk prefetch schedule: chunks 0..31 = gating_w, 32..63 = output_w.
#define XSTR 260
#define WSTR 264
#define SMEMK4_FLOATS (128 * XSTR + 4 * 8 * WSTR + 3 * 256)
#define SMEMK4 (SMEMK4_FLOATS * 4)

extern __shared__ float sm5[];
__global__ void __launch_bounds__(256, 1)
k_fused(const float* __restrict__ qd, const float* __restrict__ gb,
        const float* __restrict__ ob, float* __restrict__ out) {
    float* Xs = sm5;                       // 128*XSTR
    float* Wr = Xs + 128 * XSTR;           // 4 stages * 8 * WSTR
    float* wa_s = Wr + 4 * 8 * WSTR;
    float* gb_s = wa_s + 256;
    float* ob_s = gb_s + 256;

    int t = threadIdx.x;
    int w = t >> 5, lane = t & 31;
    int tile = blockIdx.x;
    int b = tile >> 4;
    int n0 = (tile & 15) * 128;

    uint32_t ring_u = s2u(Wr);
    int pr = t >> 6, pc = (t & 63) * 4;    // this thread's cp.async rows/cols

    // prefetch chunk s (s = 0..63); always commit so group counting stays uniform
    auto prefetch = [&](int s) {
        if (s < 64) {
            const float* W = (s < 32 ? g_gwt : g_owt) + ((s & 31) * 8 + pr) * 256 + pc;
            uint32_t d = ring_u + (uint32_t)(((s & 3) * 8 * WSTR + pr * WSTR + pc) * 4);
            cpa16(d, W);
            cpa16(d + 4 * WSTR * 4, W + 4 * 256);
        }
        asm volatile("cp.async.commit_group;" ::: "memory");
    };

    wa_s[t] = g_wa[b * 256 + t];
    gb_s[t] = gb[t];
    ob_s[t] = ob[t];

    prefetch(0); prefetch(1); prefetch(2);

    // load X tile (128x256), tf32-rounded, into Xs (stride 260)
    {
        const float* xg = qd + ((size_t)b * Nn + n0) * An;
        #pragma unroll
        for (int i = 0; i < 32; i++) {
            int f = t + 256 * i;
            int r = f >> 6, c = (f & 63) * 4;
            float4 v = *(const float4*)(xg + (size_t)r * An + c);
            *(float4*)(Xs + r * XSTR + c) =
                make_float4(tf32r(v.x), tf32r(v.y), tf32r(v.z), tf32r(v.w));
        }
    }
    __syncthreads();

    int row0 = (w & 1) * 64, col0 = (w >> 1) * 64;
    int g = lane >> 2, tg = lane & 3;

    float acc[4][8][4];
    #pragma unroll
    for (int i = 0; i < 4; i++)
        #pragma unroll
        for (int jj = 0; jj < 8; jj++)
            #pragma unroll
            for (int r = 0; r < 4; r++) acc[i][jj][r] = 0.f;

    // ---- GEMM1: X @ gating_w (chunks 0..31) ----
    for (int kc = 0; kc < 32; kc++) {
        asm volatile("cp.async.wait_group 2;" ::: "memory");
        __syncthreads();
        int kb = kc * 8;
        unsigned af[4][4];
        #pragma unroll
        for (int i = 0; i < 4; i++) {
            int r0 = row0 + i * 16 + g;
            af[i][0] = __float_as_uint(Xs[r0 * XSTR + kb + tg]);
            af[i][1] = __float_as_uint(Xs[(r0 + 8) * XSTR + kb + tg]);
            af[i][2] = __float_as_uint(Xs[r0 * XSTR + kb + tg + 4]);
            af[i][3] = __float_as_uint(Xs[(r0 + 8) * XSTR + kb + tg + 4]);
        }
        const float* Wb = Wr + (kc & 3) * 8 * WSTR;
        prefetch(kc + 3);
        #pragma unroll
        for (int jj = 0; jj < 8; jj++) {
            int col = col0 + jj * 8 + g;
            unsigned b0 = __float_as_uint(Wb[tg * WSTR + col]);
            unsigned b1 = __float_as_uint(Wb[(tg + 4) * WSTR + col]);
            #pragma unroll
            for (int i = 0; i < 4; i++) {
                asm volatile(
                    "mma.sync.aligned.m16n8k8.row.col.f32.tf32.tf32.f32 "
                    "{%0,%1,%2,%3},{%4,%5,%6,%7},{%8,%9},{%0,%1,%2,%3};"
                    : "+f"(acc[i][jj][0]), "+f"(acc[i][jj][1]),
                      "+f"(acc[i][jj][2]), "+f"(acc[i][jj][3])
                    : "r"(af[i][0]), "r"(af[i][1]), "r"(af[i][2]), "r"(af[i][3]),
                      "r"(b0), "r"(b1));
            }
        }
    }
    __syncthreads();   // all GEMM1 A-frag reads done before Xs overwrite

    // ---- epilogue1: G = sigmoid(acc + gb) * wa -> Xs (tf32) ----
    #pragma unroll
    for (int i = 0; i < 4; i++) {
        int r = row0 + i * 16 + g;
        #pragma unroll
        for (int jj = 0; jj < 8; jj++) {
            int c = col0 + jj * 8 + tg * 2;
            float w0 = wa_s[c], w1 = wa_s[c + 1];
            float b0 = gb_s[c], b1 = gb_s[c + 1];
            float v0 = w0 / (1.f + __expf(-(acc[i][jj][0] + b0)));
            float v1 = w1 / (1.f + __expf(-(acc[i][jj][1] + b1)));
            float v2 = w0 / (1.f + __expf(-(acc[i][jj][2] + b0)));
            float v3 = w1 / (1.f + __expf(-(acc[i][jj][3] + b1)));
            *(float2*)(Xs + r * XSTR + c) = make_float2(tf32r(v0), tf32r(v1));
            *(float2*)(Xs + (r + 8) * XSTR + c) = make_float2(tf32r(v2), tf32r(v3));
            acc[i][jj][0] = 0.f; acc[i][jj][1] = 0.f;
            acc[i][jj][2] = 0.f; acc[i][jj][3] = 0.f;
        }
    }
    __syncthreads();

    // ---- GEMM2: G @ output_w (chunks 32..63) ----
    for (int kc = 32; kc < 64; kc++) {
        asm volatile("cp.async.wait_group 2;" ::: "memory");
        __syncthreads();
        int kb = (kc & 31) * 8;
        unsigned af[4][4];
        #pragma unroll
        for (int i = 0; i < 4; i++) {
            int r0 = row0 + i * 16 + g;
            af[i][0] = __float_as_uint(Xs[r0 * XSTR + kb + tg]);
            af[i][1] = __float_as_uint(Xs[(r0 + 8) * XSTR + kb + tg]);
            af[i][2] = __float_as_uint(Xs[r0 * XSTR + kb + tg + 4]);
            af[i][3] = __float_as_uint(Xs[(r0 + 8) * XSTR + kb + tg + 4]);
        }
        const float* Wb = Wr + (kc & 3) * 8 * WSTR;
        prefetch(kc + 3);
        #pragma unroll
        for (int jj = 0; jj < 8; jj++) {
            int col = col0 + jj * 8 + g;
            unsigned b0 = __float_as_uint(Wb[tg * WSTR + col]);
            unsigned b1 = __float_as_uint(Wb[(tg + 4) * WSTR + col]);
            #pragma unroll
            for (int i = 0; i < 4; i++) {
                asm volatile(
                    "mma.sync.aligned.m16n8k8.row.col.f32.tf32.tf32.f32 "
                    "{%0,%1,%2,%3},{%4,%5,%6,%7},{%8,%9},{%0,%1,%2,%3};"
                    : "+f"(acc[i][jj][0]), "+f"(acc[i][jj][1]),
                      "+f"(acc[i][jj][2]), "+f"(acc[i][jj][3])
                    : "r"(af[i][0]), "r"(af[i][1]), "r"(af[i][2]), "r"(af[i][3]),
                      "r"(b0), "r"(b1));
            }
        }
    }

    // ---- epilogue2: out = acc + ob ----
    float* og = out + ((size_t)b * Nn + n0) * 256;
    #pragma unroll
    for (int i = 0; i < 4; i++) {
        int r = row0 + i * 16 + g;
        #pragma unroll
        for (int jj = 0; jj < 8; jj++) {
            int c = col0 + jj * 8 + tg * 2;
            float2 u0 = make_float2(acc[i][jj][0] + ob_s[c], acc[i][jj][1] + ob_s[c + 1]);
            float2 u1 = make_float2(acc[i][jj][2] + ob_s[c], acc[i][jj][3] + ob_s[c + 1]);
            *(float2*)(og + (size_t)r * 256 + c) = u0;
            *(float2*)(og + (size_t)(r + 8) * 256 + c) = u1;
        }
    }
}

// =====================  launch  =====================
extern "C" void kernel_launch(void* const* d_in, const int* in_sizes, int n_in,
                              void* d_out, int out_size) {
    (void)in_sizes; (void)n_in; (void)out_size;
    const float* qd = (const float*)d_in[0];   // q_data [B,N,A]
    const float* md = (const float*)d_in[1];   // m_data [B,N,M]
    const float* qm = (const float*)d_in[2];   // q_mask [B,N,1]
    const float* qw = (const float*)d_in[4];   // query_w [A,H,KD]
    const float* kw = (const float*)d_in[5];   // key_w [M,KD]
    const float* vw = (const float*)d_in[6];   // value_w [M,VD]
    const float* gw = (const float*)d_in[7];   // gating_w [A,H,VD]
    const float* gb = (const float*)d_in[8];   // gating_b [H,VD]
    const float* ow = (const float*)d_in[9];   // output_w [H,VD,O]
    const float* ob = (const float*)d_in[10];  // output_b [O]
    float* out = (float*)d_out;

    cudaFuncSetAttribute(k_attn, cudaFuncAttributeMaxDynamicSharedMemorySize, 81920);
    cudaFuncSetAttribute(k_fused, cudaFuncAttributeMaxDynamicSharedMemorySize, SMEMK4);

    k_prep<<<256, 256>>>(gw, ow);
    k_qavg<<<dim3(4, 256), 256>>>(qd, qm);
    k_qk<<<256, 256>>>(qw, kw);
    k_attn<<<256, 512, 81920>>>(md, qm, vw);
    k_fused<<<4096, 256, SMEMK4>>>(qd, gb, ob, out);
}